// round 1
// baseline (speedup 1.0000x reference)
#include <cuda_runtime.h>
#include <math.h>

#define BB 2
#define SS 2048
#define DM 1024
#define NH 16
#define HD 64

// Scratch (device globals: allocation-free per harness rules)
__device__ float g_q[BB * NH * SS * HD];     // [b][h][s][c]
__device__ float g_k[BB * NH * SS * HD];     // [b][h][s][c]
__device__ float g_v[BB * NH * SS * HD];     // [b][h][s][c]
__device__ float g_vals[BB * SS * DM];       // [b][s][h*64+c]

// ---------------------------------------------------------------------------
// SGEMM: C[M,N] = A[M,K] @ W[K,N] + bias, 128x128x16 tile, 256 threads, 8x8.
// MODE 0: scatter to g_q      (N=1024: h=c>>6,  cc=c&63)
// MODE 1: scatter to g_k/g_v  (N=2048: h=c>>7,  t=c&127; t<64->k else v)
// MODE 2: plain row-major store to Cout
// ---------------------------------------------------------------------------
template <int MODE>
__global__ __launch_bounds__(256)
void sgemm_epi(const float* __restrict__ A, const float* __restrict__ W,
               const float* __restrict__ bias, float* __restrict__ Cout,
               int M, int N, int K)
{
    __shared__ float As[16][132];   // transposed: As[k][m]
    __shared__ float Bs[16][132];   // Bs[k][n]

    const int tid  = threadIdx.x;
    const int tx   = tid & 15;
    const int ty   = tid >> 4;
    const int brow = blockIdx.y * 128;
    const int bcol = blockIdx.x * 128;

    // A load pattern: 128 rows x 16 k, 2 float4/thread
    const int arow = tid >> 2;          // 0..63
    const int acol = (tid & 3) << 2;    // 0,4,8,12
    // W load pattern: 16 k x 128 n, 2 float4/thread
    const int bR = tid >> 5;            // 0..7
    const int bC = (tid & 31) << 2;     // 0..124

    float acc[8][8];
#pragma unroll
    for (int i = 0; i < 8; i++)
#pragma unroll
        for (int j = 0; j < 8; j++) acc[i][j] = 0.f;

    for (int k0 = 0; k0 < K; k0 += 16) {
        float4 a0 = *(const float4*)(A + (size_t)(brow + arow) * K + k0 + acol);
        float4 a1 = *(const float4*)(A + (size_t)(brow + arow + 64) * K + k0 + acol);
        float4 b0 = *(const float4*)(W + (size_t)(k0 + bR) * N + bcol + bC);
        float4 b1 = *(const float4*)(W + (size_t)(k0 + bR + 8) * N + bcol + bC);

        As[acol + 0][arow] = a0.x; As[acol + 1][arow] = a0.y;
        As[acol + 2][arow] = a0.z; As[acol + 3][arow] = a0.w;
        As[acol + 0][arow + 64] = a1.x; As[acol + 1][arow + 64] = a1.y;
        As[acol + 2][arow + 64] = a1.z; As[acol + 3][arow + 64] = a1.w;
        *(float4*)&Bs[bR][bC]     = b0;
        *(float4*)&Bs[bR + 8][bC] = b1;
        __syncthreads();

#pragma unroll
        for (int kk = 0; kk < 16; kk++) {
            float af[8], bf[8];
            *(float4*)&af[0] = *(const float4*)&As[kk][ty * 4];
            *(float4*)&af[4] = *(const float4*)&As[kk][64 + ty * 4];
            *(float4*)&bf[0] = *(const float4*)&Bs[kk][tx * 4];
            *(float4*)&bf[4] = *(const float4*)&Bs[kk][64 + tx * 4];
#pragma unroll
            for (int i = 0; i < 8; i++)
#pragma unroll
                for (int j = 0; j < 8; j++)
                    acc[i][j] += af[i] * bf[j];
        }
        __syncthreads();
    }

    // Epilogue
#pragma unroll
    for (int i = 0; i < 8; i++) {
        const int r  = brow + ((i < 4) ? (ty * 4 + i) : (64 + ty * 4 + i - 4));
        const int b  = r >> 11;      // r / 2048
        const int s  = r & 2047;
#pragma unroll
        for (int j = 0; j < 8; j++) {
            const int c = bcol + ((j < 4) ? (tx * 4 + j) : (64 + tx * 4 + j - 4));
            const float val = acc[i][j] + bias[c];
            if (MODE == 0) {
                const int h = c >> 6, cc = c & 63;
                g_q[(((size_t)(b * NH + h) * SS) + s) * HD + cc] = val;
            } else if (MODE == 1) {
                const int h = c >> 7, t = c & 127;
                if (t < HD)
                    g_k[(((size_t)(b * NH + h) * SS) + s) * HD + t] = val;
                else
                    g_v[(((size_t)(b * NH + h) * SS) + s) * HD + (t - HD)] = val;
            } else {
                Cout[(size_t)r * N + c] = val;
            }
        }
    }
}

// ---------------------------------------------------------------------------
// Flash attention: 64-query block per CTA, loop over 64-key tiles.
// grid = (S/64, B*H), 256 threads. Online softmax, k-tile transposed in smem.
// ---------------------------------------------------------------------------
__global__ __launch_bounds__(256)
void attn_kernel(const float* __restrict__ mask)
{
    extern __shared__ float sm[];
    float* qs   = sm;                  // [64][68] (q, pre-scaled by 1/8)
    float* ks   = sm + 64 * 68;        // [d][r]  (k transposed)
    float* vs   = sm + 2 * 64 * 68;    // [r][c]
    float* sc   = sm + 3 * 64 * 68;    // [q][k] scores -> probs
    float* m_s  = sm + 4 * 64 * 68;    // [64]
    float* l_s  = m_s + 64;            // [64]
    float* al_s = l_s + 64;            // [64]

    const int tid = threadIdx.x;
    const int tx  = tid & 15;
    const int ty  = tid >> 4;
    const int bh  = blockIdx.y;
    const int b   = bh >> 4;
    const int h   = bh & 15;
    const int qbase = blockIdx.x * 64;

    const float* qg  = g_q + ((size_t)bh * SS + qbase) * HD;
    const float* kgb = g_k + (size_t)bh * SS * HD;
    const float* vgb = g_v + (size_t)bh * SS * HD;

    // load q tile, pre-scaled by 1/sqrt(64)
#pragma unroll
    for (int it = 0; it < 4; it++) {
        const int lin = it * 1024 + tid * 4;
        const int r = lin >> 6, c = lin & 63;
        float4 qv = *(const float4*)(qg + r * 64 + c);
        qv.x *= 0.125f; qv.y *= 0.125f; qv.z *= 0.125f; qv.w *= 0.125f;
        *(float4*)(qs + r * 68 + c) = qv;
    }
    if (tid < 64) { m_s[tid] = -1e30f; l_s[tid] = 0.f; }

    float acc[4][4];
#pragma unroll
    for (int i = 0; i < 4; i++)
#pragma unroll
        for (int j = 0; j < 4; j++) acc[i][j] = 0.f;

    __syncthreads();

    for (int kt = 0; kt < SS / 64; kt++) {
        const int kbase = kt * 64;
        // load k (transposed) and v tiles
#pragma unroll
        for (int it = 0; it < 4; it++) {
            const int lin = it * 1024 + tid * 4;
            const int r = lin >> 6, c = lin & 63;
            const float4 kv = *(const float4*)(kgb + (size_t)(kbase + r) * 64 + c);
            ks[(c + 0) * 68 + r] = kv.x;
            ks[(c + 1) * 68 + r] = kv.y;
            ks[(c + 2) * 68 + r] = kv.z;
            ks[(c + 3) * 68 + r] = kv.w;
            *(float4*)(vs + r * 68 + c) =
                *(const float4*)(vgb + (size_t)(kbase + r) * 64 + c);
        }
        __syncthreads();

        // scores: 4x4 per thread
        float s4[4][4];
#pragma unroll
        for (int i = 0; i < 4; i++)
#pragma unroll
            for (int j = 0; j < 4; j++) s4[i][j] = 0.f;

#pragma unroll 8
        for (int d = 0; d < 64; d++) {
            float qv[4], kv4[4];
#pragma unroll
            for (int i = 0; i < 4; i++) qv[i] = qs[(ty * 4 + i) * 68 + d];
#pragma unroll
            for (int j = 0; j < 4; j++) kv4[j] = ks[d * 68 + tx * 4 + j];
#pragma unroll
            for (int i = 0; i < 4; i++)
#pragma unroll
                for (int j = 0; j < 4; j++)
                    s4[i][j] += qv[i] * kv4[j];
        }
#pragma unroll
        for (int i = 0; i < 4; i++) {
            const size_t mrow = ((size_t)b * SS + (qbase + ty * 4 + i)) * SS + kbase;
#pragma unroll
            for (int j = 0; j < 4; j++)
                sc[(ty * 4 + i) * 68 + tx * 4 + j] = s4[i][j] + mask[mrow + tx * 4 + j];
        }
        __syncthreads();

        // online softmax: 4 threads per row, 16 cols each
        {
            const int r = tid >> 2;
            const int part = tid & 3;
            const int c0 = part * 16;
            float mx = -1e30f;
#pragma unroll
            for (int j = 0; j < 16; j++) mx = fmaxf(mx, sc[r * 68 + c0 + j]);
            mx = fmaxf(mx, __shfl_xor_sync(0xffffffffu, mx, 1));
            mx = fmaxf(mx, __shfl_xor_sync(0xffffffffu, mx, 2));
            const float mnew = fmaxf(m_s[r], mx);
            float sum = 0.f;
#pragma unroll
            for (int j = 0; j < 16; j++) {
                const float p = __expf(sc[r * 68 + c0 + j] - mnew);
                sc[r * 68 + c0 + j] = p;
                sum += p;
            }
            sum += __shfl_xor_sync(0xffffffffu, sum, 1);
            sum += __shfl_xor_sync(0xffffffffu, sum, 2);
            if (part == 0) {
                const float a = __expf(m_s[r] - mnew);
                al_s[r] = a;
                l_s[r]  = l_s[r] * a + sum;
                m_s[r]  = mnew;
            }
        }
        __syncthreads();

        // rescale + PV accumulate
        float ai[4];
#pragma unroll
        for (int i = 0; i < 4; i++) ai[i] = al_s[ty * 4 + i];
#pragma unroll
        for (int i = 0; i < 4; i++)
#pragma unroll
            for (int j = 0; j < 4; j++) acc[i][j] *= ai[i];

#pragma unroll 8
        for (int kk = 0; kk < 64; kk++) {
            float pv[4], vv[4];
#pragma unroll
            for (int i = 0; i < 4; i++) pv[i] = sc[(ty * 4 + i) * 68 + kk];
#pragma unroll
            for (int j = 0; j < 4; j++) vv[j] = vs[kk * 68 + tx * 4 + j];
#pragma unroll
            for (int i = 0; i < 4; i++)
#pragma unroll
                for (int j = 0; j < 4; j++)
                    acc[i][j] += pv[i] * vv[j];
        }
        __syncthreads();
    }

    // write vals in (B,S,D) layout
#pragma unroll
    for (int i = 0; i < 4; i++) {
        const float inv = 1.0f / l_s[ty * 4 + i];
        float* orow = g_vals + ((size_t)b * SS + (qbase + ty * 4 + i)) * DM + h * HD + tx * 4;
#pragma unroll
        for (int j = 0; j < 4; j++)
            orow[j] = acc[i][j] * inv;
    }
}

// ---------------------------------------------------------------------------
extern "C" void kernel_launch(void* const* d_in, const int* in_sizes, int n_in,
                              void* d_out, int out_size)
{
    const float* x    = (const float*)d_in[0];
    const float* y    = (const float*)d_in[1];
    const float* mask = (const float*)d_in[2];
    const float* Wkv  = (const float*)d_in[3];
    const float* bkv  = (const float*)d_in[4];
    const float* Wq   = (const float*)d_in[5];
    const float* bq   = (const float*)d_in[6];
    const float* Wo   = (const float*)d_in[7];
    const float* bo   = (const float*)d_in[8];
    float* out = (float*)d_out;

    float* vals_ptr = nullptr;
    cudaGetSymbolAddress((void**)&vals_ptr, g_vals);

    const dim3 blk(256);
    const int M = BB * SS;  // 4096

    // q projection
    sgemm_epi<0><<<dim3(DM / 128, M / 128), blk>>>(y, Wq, bq, nullptr, M, DM, DM);
    // kv projection
    sgemm_epi<1><<<dim3(2 * DM / 128, M / 128), blk>>>(x, Wkv, bkv, nullptr, M, 2 * DM, DM);

    // attention
    const size_t smem = (size_t)(4 * 64 * 68 + 3 * 64) * sizeof(float);  // 70400 B
    cudaFuncSetAttribute(attn_kernel, cudaFuncAttributeMaxDynamicSharedMemorySize, (int)smem);
    attn_kernel<<<dim3(SS / 64, BB * NH), blk, smem>>>(mask);

    // output projection
    sgemm_epi<2><<<dim3(DM / 128, M / 128), blk>>>(vals_ptr, Wo, bo, out, M, DM, DM);
}

// round 2
// speedup vs baseline: 2.0659x; 2.0659x over previous
#include <cuda_runtime.h>
#include <math.h>

#define BB 2
#define SS 2048
#define DM 1024
#define NH 16
#define HD 64

// Scratch (device globals: allocation-free per harness rules)
__device__ float g_q[BB * NH * SS * HD];     // [b][h][s][c]
__device__ float g_k[BB * NH * SS * HD];     // [b][h][s][c]
__device__ float g_v[BB * NH * SS * HD];     // [b][h][s][c]
__device__ float g_vals[BB * SS * DM];       // [b][s][h*64+c]

// ---------------------------------------------------------------------------
// tf32 helpers
// ---------------------------------------------------------------------------
__device__ __forceinline__ float f2tf(float f) {
    unsigned u;
    asm("cvt.rna.tf32.f32 %0, %1;" : "=r"(u) : "f"(f));
    return __uint_as_float(u);
}

__device__ __forceinline__ void mma8(float* d, const unsigned* a, const unsigned* b)
{
    asm volatile(
        "mma.sync.aligned.m16n8k8.row.col.f32.tf32.tf32.f32 "
        "{%0,%1,%2,%3},{%4,%5,%6,%7},{%8,%9},{%0,%1,%2,%3};"
        : "+f"(d[0]), "+f"(d[1]), "+f"(d[2]), "+f"(d[3])
        : "r"(a[0]), "r"(a[1]), "r"(a[2]), "r"(a[3]),
          "r"(b[0]), "r"(b[1]));
}

// ---------------------------------------------------------------------------
// tf32 GEMM: C[M,N] = A[M,K] @ W[K,N] + bias. 128x128x16 tile, 8 warps,
// warp tile 64x32 (m-frags 4, n-frags 4), mma.m16n8k8.
// MODE 0: scatter to g_q; MODE 1: scatter g_k/g_v; MODE 2: row-major out.
// ---------------------------------------------------------------------------
template <int MODE>
__device__ __forceinline__ void store_out(int r, int c, float val,
                                          float* __restrict__ Cout, int N)
{
    const int b = r >> 11;     // r / 2048
    const int s = r & 2047;
    if (MODE == 0) {
        const int h = c >> 6, cc = c & 63;
        g_q[(((size_t)(b * NH + h) * SS) + s) * HD + cc] = val;
    } else if (MODE == 1) {
        const int h = c >> 7, t = c & 127;
        if (t < HD)
            g_k[(((size_t)(b * NH + h) * SS) + s) * HD + t] = val;
        else
            g_v[(((size_t)(b * NH + h) * SS) + s) * HD + (t - HD)] = val;
    } else {
        Cout[(size_t)r * N + c] = val;
    }
}

template <int MODE>
__global__ __launch_bounds__(256)
void gemm_tf32(const float* __restrict__ A, const float* __restrict__ W,
               const float* __restrict__ bias, float* __restrict__ Cout,
               int M, int N, int K)
{
    __shared__ float As[16][132];   // [k][m], tf32-rounded
    __shared__ float Bs[16][132];   // [k][n], tf32-rounded

    const int tid  = threadIdx.x;
    const int lane = tid & 31;
    const int w    = tid >> 5;
    const int g    = lane >> 2;     // 0..7
    const int q    = lane & 3;      // 0..3
    const int wm   = (w >> 2) * 64; // warp row offset in tile
    const int wn   = (w & 3) * 32;  // warp col offset in tile

    const int brow = blockIdx.y * 128;
    const int bcol = blockIdx.x * 128;

    const int arow = tid >> 2;          // 0..63
    const int acol = (tid & 3) << 2;    // 0,4,8,12
    const int bR   = tid >> 5;          // 0..7
    const int bC   = (tid & 31) << 2;   // 0..124

    float acc[4][4][4];
#pragma unroll
    for (int mi = 0; mi < 4; mi++)
#pragma unroll
        for (int ni = 0; ni < 4; ni++)
#pragma unroll
            for (int e = 0; e < 4; e++) acc[mi][ni][e] = 0.f;

    for (int k0 = 0; k0 < K; k0 += 16) {
        float4 a0 = *(const float4*)(A + (size_t)(brow + arow) * K + k0 + acol);
        float4 a1 = *(const float4*)(A + (size_t)(brow + arow + 64) * K + k0 + acol);
        float4 b0 = *(const float4*)(W + (size_t)(k0 + bR) * N + bcol + bC);
        float4 b1 = *(const float4*)(W + (size_t)(k0 + bR + 8) * N + bcol + bC);

        As[acol + 0][arow] = f2tf(a0.x); As[acol + 1][arow] = f2tf(a0.y);
        As[acol + 2][arow] = f2tf(a0.z); As[acol + 3][arow] = f2tf(a0.w);
        As[acol + 0][arow + 64] = f2tf(a1.x); As[acol + 1][arow + 64] = f2tf(a1.y);
        As[acol + 2][arow + 64] = f2tf(a1.z); As[acol + 3][arow + 64] = f2tf(a1.w);
        float4 tb0 = make_float4(f2tf(b0.x), f2tf(b0.y), f2tf(b0.z), f2tf(b0.w));
        float4 tb1 = make_float4(f2tf(b1.x), f2tf(b1.y), f2tf(b1.z), f2tf(b1.w));
        *(float4*)&Bs[bR][bC]     = tb0;
        *(float4*)&Bs[bR + 8][bC] = tb1;
        __syncthreads();

#pragma unroll
        for (int ks = 0; ks < 2; ks++) {
            const int kk = ks * 8;
            unsigned af[4][4];
#pragma unroll
            for (int mi = 0; mi < 4; mi++) {
                const int m0 = wm + mi * 16;
                af[mi][0] = __float_as_uint(As[kk + q][m0 + g]);
                af[mi][1] = __float_as_uint(As[kk + q][m0 + g + 8]);
                af[mi][2] = __float_as_uint(As[kk + q + 4][m0 + g]);
                af[mi][3] = __float_as_uint(As[kk + q + 4][m0 + g + 8]);
            }
            unsigned bf[4][2];
#pragma unroll
            for (int ni = 0; ni < 4; ni++) {
                const int n0 = wn + ni * 8;
                bf[ni][0] = __float_as_uint(Bs[kk + q][n0 + g]);
                bf[ni][1] = __float_as_uint(Bs[kk + q + 4][n0 + g]);
            }
#pragma unroll
            for (int mi = 0; mi < 4; mi++)
#pragma unroll
                for (int ni = 0; ni < 4; ni++)
                    mma8(acc[mi][ni], af[mi], bf[ni]);
        }
        __syncthreads();
    }

    // Epilogue: frag (r,c): c0=(g,2q) c1=(g,2q+1) c2=(g+8,2q) c3=(g+8,2q+1)
#pragma unroll
    for (int mi = 0; mi < 4; mi++) {
        const int r0 = brow + wm + mi * 16 + g;
        const int r1 = r0 + 8;
#pragma unroll
        for (int ni = 0; ni < 4; ni++) {
            const int c0 = bcol + wn + ni * 8 + 2 * q;
            const float bia0 = bias[c0], bia1 = bias[c0 + 1];
            store_out<MODE>(r0, c0,     acc[mi][ni][0] + bia0, Cout, N);
            store_out<MODE>(r0, c0 + 1, acc[mi][ni][1] + bia1, Cout, N);
            store_out<MODE>(r1, c0,     acc[mi][ni][2] + bia0, Cout, N);
            store_out<MODE>(r1, c0 + 1, acc[mi][ni][3] + bia1, Cout, N);
        }
    }
}

// ---------------------------------------------------------------------------
// Flash attention (tf32 mma): 128-q block per CTA, 8 warps (16 q rows each),
// key tiles of 32. Online softmax in registers. P -> smem -> PV mma.
// ---------------------------------------------------------------------------
__global__ __launch_bounds__(256)
void attn_tf32(const float* __restrict__ mask)
{
    extern __shared__ float sm[];
    float (*qs)[68] = (float(*)[68])sm;                      // 128 x 68
    float (*ks)[68] = (float(*)[68])(sm + 128 * 68);         // 32 x 68
    float (*vs)[68] = (float(*)[68])(sm + 160 * 68);         // 32 x 68
    float (*ps)[36] = (float(*)[36])(sm + 192 * 68);         // 128 x 36

    const int tid  = threadIdx.x;
    const int lane = tid & 31;
    const int w    = tid >> 5;
    const int g    = lane >> 2;
    const int q    = lane & 3;

    const int bh    = blockIdx.y;
    const int b     = bh >> 4;
    const int h     = bh & 15;
    const int qbase = blockIdx.x * 128;

    const float* qg  = g_q + ((size_t)bh * SS + qbase) * HD;
    const float* kgb = g_k + (size_t)bh * SS * HD;
    const float* vgb = g_v + (size_t)bh * SS * HD;

    // load q tile (pre-scaled by 1/sqrt(64), tf32 rounded)
#pragma unroll
    for (int it = 0; it < 8; it++) {
        const int lin = it * 1024 + tid * 4;
        const int r = lin >> 6, c = lin & 63;
        float4 qv = *(const float4*)(qg + r * 64 + c);
        qs[r][c + 0] = f2tf(qv.x * 0.125f);
        qs[r][c + 1] = f2tf(qv.y * 0.125f);
        qs[r][c + 2] = f2tf(qv.z * 0.125f);
        qs[r][c + 3] = f2tf(qv.w * 0.125f);
    }

    float oacc[8][4];
#pragma unroll
    for (int ni = 0; ni < 8; ni++)
#pragma unroll
        for (int e = 0; e < 4; e++) oacc[ni][e] = 0.f;
    float m0 = -1e30f, m1 = -1e30f, l0 = 0.f, l1 = 0.f;

    const int qrow0 = w * 16 + g;     // local row of c0/c1
    const int qrow1 = qrow0 + 8;      // local row of c2/c3
    const float* mrow0 = mask + ((size_t)b * SS + qbase + qrow0) * SS;
    const float* mrow1 = mask + ((size_t)b * SS + qbase + qrow1) * SS;

    __syncthreads();

    for (int kt = 0; kt < SS / 32; kt++) {
        const int kbase = kt * 32;
        // load k/v tiles (32 x 64 each), tf32 rounded
#pragma unroll
        for (int it = 0; it < 2; it++) {
            const int lin = it * 1024 + tid * 4;
            const int r = lin >> 6, c = lin & 63;
            float4 kv = *(const float4*)(kgb + (size_t)(kbase + r) * 64 + c);
            ks[r][c + 0] = f2tf(kv.x); ks[r][c + 1] = f2tf(kv.y);
            ks[r][c + 2] = f2tf(kv.z); ks[r][c + 3] = f2tf(kv.w);
            float4 vv = *(const float4*)(vgb + (size_t)(kbase + r) * 64 + c);
            vs[r][c + 0] = f2tf(vv.x); vs[r][c + 1] = f2tf(vv.y);
            vs[r][c + 2] = f2tf(vv.z); vs[r][c + 3] = f2tf(vv.w);
        }
        __syncthreads();

        // S = Q K^T  (16 x 32 per warp)
        float sacc[4][4];
#pragma unroll
        for (int ni = 0; ni < 4; ni++)
#pragma unroll
            for (int e = 0; e < 4; e++) sacc[ni][e] = 0.f;

#pragma unroll
        for (int d0 = 0; d0 < 8; d0++) {
            const int kk = d0 * 8;
            unsigned af[4];
            af[0] = __float_as_uint(qs[qrow0][kk + q]);
            af[1] = __float_as_uint(qs[qrow1][kk + q]);
            af[2] = __float_as_uint(qs[qrow0][kk + q + 4]);
            af[3] = __float_as_uint(qs[qrow1][kk + q + 4]);
#pragma unroll
            for (int ni = 0; ni < 4; ni++) {
                unsigned bf[2];
                bf[0] = __float_as_uint(ks[ni * 8 + g][kk + q]);
                bf[1] = __float_as_uint(ks[ni * 8 + g][kk + q + 4]);
                mma8(sacc[ni], af, bf);
            }
        }

        // + mask
#pragma unroll
        for (int ni = 0; ni < 4; ni++) {
            const int col = kbase + ni * 8 + 2 * q;
            const float2 mv0 = *(const float2*)(mrow0 + col);
            const float2 mv1 = *(const float2*)(mrow1 + col);
            sacc[ni][0] += mv0.x; sacc[ni][1] += mv0.y;
            sacc[ni][2] += mv1.x; sacc[ni][3] += mv1.y;
        }

        // online softmax (rows qrow0, qrow1); row spread over quad lanes
        float mx0 = fmaxf(fmaxf(sacc[0][0], sacc[0][1]), fmaxf(sacc[1][0], sacc[1][1]));
        mx0 = fmaxf(mx0, fmaxf(fmaxf(sacc[2][0], sacc[2][1]), fmaxf(sacc[3][0], sacc[3][1])));
        float mx1 = fmaxf(fmaxf(sacc[0][2], sacc[0][3]), fmaxf(sacc[1][2], sacc[1][3]));
        mx1 = fmaxf(mx1, fmaxf(fmaxf(sacc[2][2], sacc[2][3]), fmaxf(sacc[3][2], sacc[3][3])));
        mx0 = fmaxf(mx0, __shfl_xor_sync(0xffffffffu, mx0, 1));
        mx0 = fmaxf(mx0, __shfl_xor_sync(0xffffffffu, mx0, 2));
        mx1 = fmaxf(mx1, __shfl_xor_sync(0xffffffffu, mx1, 1));
        mx1 = fmaxf(mx1, __shfl_xor_sync(0xffffffffu, mx1, 2));

        const float mn0 = fmaxf(m0, mx0);
        const float mn1 = fmaxf(m1, mx1);
        const float al0 = __expf(m0 - mn0);
        const float al1 = __expf(m1 - mn1);
        float sum0 = 0.f, sum1 = 0.f;
#pragma unroll
        for (int ni = 0; ni < 4; ni++) {
            sacc[ni][0] = __expf(sacc[ni][0] - mn0); sum0 += sacc[ni][0];
            sacc[ni][1] = __expf(sacc[ni][1] - mn0); sum0 += sacc[ni][1];
            sacc[ni][2] = __expf(sacc[ni][2] - mn1); sum1 += sacc[ni][2];
            sacc[ni][3] = __expf(sacc[ni][3] - mn1); sum1 += sacc[ni][3];
        }
        sum0 += __shfl_xor_sync(0xffffffffu, sum0, 1);
        sum0 += __shfl_xor_sync(0xffffffffu, sum0, 2);
        sum1 += __shfl_xor_sync(0xffffffffu, sum1, 1);
        sum1 += __shfl_xor_sync(0xffffffffu, sum1, 2);
        l0 = l0 * al0 + sum0; m0 = mn0;
        l1 = l1 * al1 + sum1; m1 = mn1;

        // rescale O
#pragma unroll
        for (int ni = 0; ni < 8; ni++) {
            oacc[ni][0] *= al0; oacc[ni][1] *= al0;
            oacc[ni][2] *= al1; oacc[ni][3] *= al1;
        }

        // P -> smem (tf32), warp-private rows
#pragma unroll
        for (int ni = 0; ni < 4; ni++) {
            const int col = ni * 8 + 2 * q;
            ps[qrow0][col]     = f2tf(sacc[ni][0]);
            ps[qrow0][col + 1] = f2tf(sacc[ni][1]);
            ps[qrow1][col]     = f2tf(sacc[ni][2]);
            ps[qrow1][col + 1] = f2tf(sacc[ni][3]);
        }
        __syncwarp();

        // O += P V  (k-dim = 32 keys, 4 steps of 8)
#pragma unroll
        for (int kk4 = 0; kk4 < 4; kk4++) {
            const int kk = kk4 * 8;
            unsigned af[4];
            af[0] = __float_as_uint(ps[qrow0][kk + q]);
            af[1] = __float_as_uint(ps[qrow1][kk + q]);
            af[2] = __float_as_uint(ps[qrow0][kk + q + 4]);
            af[3] = __float_as_uint(ps[qrow1][kk + q + 4]);
#pragma unroll
            for (int ni = 0; ni < 8; ni++) {
                unsigned bf[2];
                bf[0] = __float_as_uint(vs[kk + q][ni * 8 + g]);
                bf[1] = __float_as_uint(vs[kk + q + 4][ni * 8 + g]);
                mma8(oacc[ni], af, bf);
            }
        }
        __syncthreads();
    }

    // epilogue: divide by l, write to g_vals (B,S,D)
    const float inv0 = 1.0f / l0;
    const float inv1 = 1.0f / l1;
    float* orow0 = g_vals + ((size_t)b * SS + qbase + qrow0) * DM + h * HD;
    float* orow1 = g_vals + ((size_t)b * SS + qbase + qrow1) * DM + h * HD;
#pragma unroll
    for (int ni = 0; ni < 8; ni++) {
        const int col = ni * 8 + 2 * q;
        *(float2*)(orow0 + col) = make_float2(oacc[ni][0] * inv0, oacc[ni][1] * inv0);
        *(float2*)(orow1 + col) = make_float2(oacc[ni][2] * inv1, oacc[ni][3] * inv1);
    }
}

// ---------------------------------------------------------------------------
extern "C" void kernel_launch(void* const* d_in, const int* in_sizes, int n_in,
                              void* d_out, int out_size)
{
    const float* x    = (const float*)d_in[0];
    const float* y    = (const float*)d_in[1];
    const float* mask = (const float*)d_in[2];
    const float* Wkv  = (const float*)d_in[3];
    const float* bkv  = (const float*)d_in[4];
    const float* Wq   = (const float*)d_in[5];
    const float* bq   = (const float*)d_in[6];
    const float* Wo   = (const float*)d_in[7];
    const float* bo   = (const float*)d_in[8];
    float* out = (float*)d_out;

    float* vals_ptr = nullptr;
    cudaGetSymbolAddress((void**)&vals_ptr, g_vals);

    const dim3 blk(256);
    const int M = BB * SS;  // 4096

    gemm_tf32<0><<<dim3(DM / 128, M / 128), blk>>>(y, Wq, bq, nullptr, M, DM, DM);
    gemm_tf32<1><<<dim3(2 * DM / 128, M / 128), blk>>>(x, Wkv, bkv, nullptr, M, 2 * DM, DM);

    const size_t smem = (size_t)(192 * 68 + 128 * 36) * sizeof(float);  // 70656 B
    cudaFuncSetAttribute(attn_tf32, cudaFuncAttributeMaxDynamicSharedMemorySize, (int)smem);
    attn_tf32<<<dim3(SS / 128, BB * NH), blk, smem>>>(mask);

    gemm_tf32<2><<<dim3(DM / 128, M / 128), blk>>>(vals_ptr, Wo, bo, out, M, DM, DM);
}

// round 4
// speedup vs baseline: 3.2344x; 1.5656x over previous
#include <cuda_runtime.h>
#include <cuda_fp16.h>
#include <cstdint>
#include <math.h>

#define BB 2
#define SS 2048
#define DM 1024
#define NH 16
#define HD 64

// fp16 scratch (device globals: allocation-free per harness rules)
__device__ __half g_q[BB * NH * SS * HD];     // [b][h][s][c], pre-scaled by 1/8
__device__ __half g_k[BB * NH * SS * HD];     // [b][h][s][c]
__device__ __half g_v[BB * NH * SS * HD];     // [b][h][s][c]
__device__ __half g_vals[BB * SS * DM];       // [b][s][h*64+c]

// ---------------------------------------------------------------------------
// helpers
// ---------------------------------------------------------------------------
__device__ __forceinline__ unsigned pkh(float a, float b) {
    __half2 h = __floats2half2_rn(a, b);
    return *reinterpret_cast<unsigned*>(&h);
}
__device__ __forceinline__ unsigned sptr(const void* p) {
    return (unsigned)__cvta_generic_to_shared(p);
}
__device__ __forceinline__ void ldsm4(unsigned* r, unsigned addr) {
    asm volatile("ldmatrix.sync.aligned.m8n8.x4.shared.b16 {%0,%1,%2,%3},[%4];"
                 : "=r"(r[0]), "=r"(r[1]), "=r"(r[2]), "=r"(r[3]) : "r"(addr));
}
__device__ __forceinline__ void ldsm4t(unsigned* r, unsigned addr) {
    asm volatile("ldmatrix.sync.aligned.m8n8.x4.trans.shared.b16 {%0,%1,%2,%3},[%4];"
                 : "=r"(r[0]), "=r"(r[1]), "=r"(r[2]), "=r"(r[3]) : "r"(addr));
}
__device__ __forceinline__ void mma16(float* d, const unsigned* a, const unsigned* b) {
    asm volatile(
        "mma.sync.aligned.m16n8k16.row.col.f32.f16.f16.f32 "
        "{%0,%1,%2,%3},{%4,%5,%6,%7},{%8,%9},{%0,%1,%2,%3};"
        : "+f"(d[0]), "+f"(d[1]), "+f"(d[2]), "+f"(d[3])
        : "r"(a[0]), "r"(a[1]), "r"(a[2]), "r"(a[3]), "r"(b[0]), "r"(b[1]));
}

// ---------------------------------------------------------------------------
// fp16 GEMM: C[M,N] = A[M,K] @ W[K,N] + bias. 128x128 tile, K-chunk 32,
// 8 warps (2m x 4n), warp tile 64x32, mma.m16n8k16 + ldmatrix.
// MODE 0: scatter g_q (x0.125); MODE 1: scatter g_k/g_v; MODE 2: fp32 out.
// AHALF: A operand is __half in gmem (else fp32, converted on the fly).
// ---------------------------------------------------------------------------
template <int MODE>
__device__ __forceinline__ void store2(int r, int c0, float v0, float v1,
                                       float* __restrict__ Cout, int N)
{
    const int b = r >> 11;
    const int s = r & 2047;
    if (MODE == 0) {
        const int h = c0 >> 6, cc = c0 & 63;
        const size_t idx = (((size_t)(b * NH + h) * SS) + s) * HD + cc;
        *(unsigned*)&g_q[idx] = pkh(v0 * 0.125f, v1 * 0.125f);
    } else if (MODE == 1) {
        const int h = c0 >> 7, t = c0 & 127;
        if (t < HD) {
            const size_t idx = (((size_t)(b * NH + h) * SS) + s) * HD + t;
            *(unsigned*)&g_k[idx] = pkh(v0, v1);
        } else {
            const size_t idx = (((size_t)(b * NH + h) * SS) + s) * HD + (t - HD);
            *(unsigned*)&g_v[idx] = pkh(v0, v1);
        }
    } else {
        *(float2*)&Cout[(size_t)r * N + c0] = make_float2(v0, v1);
    }
}

template <int MODE, bool AHALF>
__global__ __launch_bounds__(256)
void gemm_h(const void* __restrict__ Av, const float* __restrict__ W,
            const float* __restrict__ bias, float* __restrict__ Cout,
            int N, int K)
{
    __shared__ __half As[128][40];
    __shared__ __half Bs[32][136];

    const int tid  = threadIdx.x;
    const int lane = tid & 31;
    const int w    = tid >> 5;
    const int wm   = (w >> 2) * 64;
    const int wn   = (w & 3) * 32;

    const int brow = blockIdx.y * 128;
    const int bcol = blockIdx.x * 128;

    const int ar = tid >> 1;            // 0..127
    const int ac = (tid & 1) * 16;      // 0,16
    const int br = tid >> 3;            // 0..31
    const int bc = (tid & 7) * 16;      // 0..112

    const float*  Af = (const float*)Av;
    const __half* Ah = (const __half*)Av;

    float acc[4][4][4];
#pragma unroll
    for (int mi = 0; mi < 4; mi++)
#pragma unroll
        for (int ni = 0; ni < 4; ni++)
#pragma unroll
            for (int e = 0; e < 4; e++) acc[mi][ni][e] = 0.f;

    float4 pa[4];
    uint4  pah[2];
    float4 pb[4];

    // prefetch k0 = 0
    if (AHALF) {
        pah[0] = *(const uint4*)(Ah + (size_t)(brow + ar) * K + ac);
        pah[1] = *(const uint4*)(Ah + (size_t)(brow + ar) * K + ac + 8);
    } else {
#pragma unroll
        for (int i = 0; i < 4; i++)
            pa[i] = *(const float4*)(Af + (size_t)(brow + ar) * K + ac + i * 4);
    }
#pragma unroll
    for (int i = 0; i < 4; i++)
        pb[i] = *(const float4*)(W + (size_t)br * N + bcol + bc + i * 4);

    for (int k0 = 0; k0 < K; k0 += 32) {
        // store staged chunk to smem
        if (AHALF) {
            *(uint4*)&As[ar][ac]     = pah[0];
            *(uint4*)&As[ar][ac + 8] = pah[1];
        } else {
            uint4 u0, u1;
            u0.x = pkh(pa[0].x, pa[0].y); u0.y = pkh(pa[0].z, pa[0].w);
            u0.z = pkh(pa[1].x, pa[1].y); u0.w = pkh(pa[1].z, pa[1].w);
            u1.x = pkh(pa[2].x, pa[2].y); u1.y = pkh(pa[2].z, pa[2].w);
            u1.z = pkh(pa[3].x, pa[3].y); u1.w = pkh(pa[3].z, pa[3].w);
            *(uint4*)&As[ar][ac]     = u0;
            *(uint4*)&As[ar][ac + 8] = u1;
        }
        {
            uint4 u0, u1;
            u0.x = pkh(pb[0].x, pb[0].y); u0.y = pkh(pb[0].z, pb[0].w);
            u0.z = pkh(pb[1].x, pb[1].y); u0.w = pkh(pb[1].z, pb[1].w);
            u1.x = pkh(pb[2].x, pb[2].y); u1.y = pkh(pb[2].z, pb[2].w);
            u1.z = pkh(pb[3].x, pb[3].y); u1.w = pkh(pb[3].z, pb[3].w);
            *(uint4*)&Bs[br][bc]     = u0;
            *(uint4*)&Bs[br][bc + 8] = u1;
        }
        __syncthreads();

        // prefetch next chunk
        if (k0 + 32 < K) {
            const int kn = k0 + 32;
            if (AHALF) {
                pah[0] = *(const uint4*)(Ah + (size_t)(brow + ar) * K + kn + ac);
                pah[1] = *(const uint4*)(Ah + (size_t)(brow + ar) * K + kn + ac + 8);
            } else {
#pragma unroll
                for (int i = 0; i < 4; i++)
                    pa[i] = *(const float4*)(Af + (size_t)(brow + ar) * K + kn + ac + i * 4);
            }
#pragma unroll
            for (int i = 0; i < 4; i++)
                pb[i] = *(const float4*)(W + (size_t)(kn + br) * N + bcol + bc + i * 4);
        }

        // compute 2 x k16
#pragma unroll
        for (int ks2 = 0; ks2 < 2; ks2++) {
            const int kk = ks2 * 16;
            unsigned af[4][4];
#pragma unroll
            for (int mi = 0; mi < 4; mi++)
                ldsm4(af[mi], sptr(&As[wm + mi * 16 + (lane & 15)][kk + ((lane >> 4) << 3)]));
            unsigned bfr[2][4];
#pragma unroll
            for (int np = 0; np < 2; np++) {
                const int row = kk + (lane & 7) + (((lane >> 3) & 1) << 3);
                const int col = wn + np * 16 + ((lane >> 4) << 3);
                ldsm4t(bfr[np], sptr(&Bs[row][col]));
            }
#pragma unroll
            for (int mi = 0; mi < 4; mi++)
#pragma unroll
                for (int ni = 0; ni < 4; ni++)
                    mma16(acc[mi][ni], af[mi], &bfr[ni >> 1][(ni & 1) * 2]);
        }
        __syncthreads();
    }

    // epilogue
    const int g = lane >> 2, q = lane & 3;
#pragma unroll
    for (int mi = 0; mi < 4; mi++) {
        const int r0 = brow + wm + mi * 16 + g;
        const int r1 = r0 + 8;
#pragma unroll
        for (int ni = 0; ni < 4; ni++) {
            const int c0 = bcol + wn + ni * 8 + 2 * q;
            const float bia0 = bias[c0], bia1 = bias[c0 + 1];
            store2<MODE>(r0, c0, acc[mi][ni][0] + bia0, acc[mi][ni][1] + bia1, Cout, N);
            store2<MODE>(r1, c0, acc[mi][ni][2] + bia0, acc[mi][ni][3] + bia1, Cout, N);
        }
    }
}

// ---------------------------------------------------------------------------
// Flash attention fp16: 128 q-rows/CTA, 8 warps (16 rows each), key tile 64.
// QK via mma16, P stays in registers as A-fragments for PV. Online softmax.
// ---------------------------------------------------------------------------
__global__ __launch_bounds__(256)
void attn_h(const float* __restrict__ mask)
{
    __shared__ __half qs[128][72];
    __shared__ __half ks[64][72];
    __shared__ __half vs[64][72];

    const int tid  = threadIdx.x;
    const int lane = tid & 31;
    const int w    = tid >> 5;
    const int g    = lane >> 2;
    const int q    = lane & 3;

    const int bh    = blockIdx.y;
    const int b     = bh >> 4;
    const int h     = bh & 15;
    const int qbase = blockIdx.x * 128;

    const __half* qg  = g_q + ((size_t)bh * SS + qbase) * HD;
    const __half* kgb = g_k + (size_t)bh * SS * HD;
    const __half* vgb = g_v + (size_t)bh * SS * HD;

    // load q tile (pure copy; already fp16 + pre-scaled)
    {
        const int r = tid >> 1, cs = (tid & 1) * 32;
#pragma unroll
        for (int i = 0; i < 4; i++)
            *(uint4*)&qs[r][cs + i * 8] = *(const uint4*)(qg + (size_t)r * HD + cs + i * 8);
    }
    __syncthreads();

    // hoist q a-fragments (invariant across key tiles)
    unsigned qa[4][4];
#pragma unroll
    for (int kk4 = 0; kk4 < 4; kk4++)
        ldsm4(qa[kk4], sptr(&qs[w * 16 + (lane & 15)][kk4 * 16 + ((lane >> 4) << 3)]));

    float oacc[8][4];
#pragma unroll
    for (int ni = 0; ni < 8; ni++)
#pragma unroll
        for (int e = 0; e < 4; e++) oacc[ni][e] = 0.f;
    float m0 = -1e30f, m1 = -1e30f, l0 = 0.f, l1 = 0.f;

    const int qrow0 = w * 16 + g;
    const int qrow1 = qrow0 + 8;
    const float* mrow0 = mask + ((size_t)b * SS + qbase + qrow0) * SS;
    const float* mrow1 = mask + ((size_t)b * SS + qbase + qrow1) * SS;

    const int tr = tid >> 2;            // 0..63
    const int tc = (tid & 3) * 16;      // 0,16,32,48

    // prefetch tile 0
    uint4 kreg[2], vreg[2];
#pragma unroll
    for (int i = 0; i < 2; i++) {
        kreg[i] = *(const uint4*)(kgb + (size_t)tr * HD + tc + i * 8);
        vreg[i] = *(const uint4*)(vgb + (size_t)tr * HD + tc + i * 8);
    }

    for (int kt = 0; kt < SS / 64; kt++) {
        const int kbase = kt * 64;
        *(uint4*)&ks[tr][tc]     = kreg[0];
        *(uint4*)&ks[tr][tc + 8] = kreg[1];
        *(uint4*)&vs[tr][tc]     = vreg[0];
        *(uint4*)&vs[tr][tc + 8] = vreg[1];
        __syncthreads();

        if (kt + 1 < SS / 64) {
            const size_t off = (size_t)(kbase + 64 + tr) * HD + tc;
#pragma unroll
            for (int i = 0; i < 2; i++) {
                kreg[i] = *(const uint4*)(kgb + off + i * 8);
                vreg[i] = *(const uint4*)(vgb + off + i * 8);
            }
        }

        // ---- S = Q K^T (16 x 64 per warp)
        float sacc[8][4];
#pragma unroll
        for (int ni = 0; ni < 8; ni++)
#pragma unroll
            for (int e = 0; e < 4; e++) sacc[ni][e] = 0.f;

#pragma unroll
        for (int kk4 = 0; kk4 < 4; kk4++) {
#pragma unroll
            for (int np = 0; np < 4; np++) {
                unsigned kb[4];
                const int row = np * 16 + (lane & 7) + (((lane >> 4) & 1) << 3);
                const int col = kk4 * 16 + (((lane >> 3) & 1) << 3);
                ldsm4(kb, sptr(&ks[row][col]));
                mma16(sacc[np * 2],     qa[kk4], &kb[0]);
                mma16(sacc[np * 2 + 1], qa[kk4], &kb[2]);
            }
        }

        // ---- + mask
#pragma unroll
        for (int ni = 0; ni < 8; ni++) {
            const int col = kbase + ni * 8 + 2 * q;
            const float2 mv0 = *(const float2*)(mrow0 + col);
            const float2 mv1 = *(const float2*)(mrow1 + col);
            sacc[ni][0] += mv0.x; sacc[ni][1] += mv0.y;
            sacc[ni][2] += mv1.x; sacc[ni][3] += mv1.y;
        }

        // ---- online softmax
        float mx0 = -1e30f, mx1 = -1e30f;
#pragma unroll
        for (int ni = 0; ni < 8; ni++) {
            mx0 = fmaxf(mx0, fmaxf(sacc[ni][0], sacc[ni][1]));
            mx1 = fmaxf(mx1, fmaxf(sacc[ni][2], sacc[ni][3]));
        }
        mx0 = fmaxf(mx0, __shfl_xor_sync(0xffffffffu, mx0, 1));
        mx0 = fmaxf(mx0, __shfl_xor_sync(0xffffffffu, mx0, 2));
        mx1 = fmaxf(mx1, __shfl_xor_sync(0xffffffffu, mx1, 1));
        mx1 = fmaxf(mx1, __shfl_xor_sync(0xffffffffu, mx1, 2));

        const float mn0 = fmaxf(m0, mx0);
        const float mn1 = fmaxf(m1, mx1);
        const float al0 = __expf(m0 - mn0);
        const float al1 = __expf(m1 - mn1);
        float sum0 = 0.f, sum1 = 0.f;
#pragma unroll
        for (int ni = 0; ni < 8; ni++) {
            sacc[ni][0] = __expf(sacc[ni][0] - mn0); sum0 += sacc[ni][0];
            sacc[ni][1] = __expf(sacc[ni][1] - mn0); sum0 += sacc[ni][1];
            sacc[ni][2] = __expf(sacc[ni][2] - mn1); sum1 += sacc[ni][2];
            sacc[ni][3] = __expf(sacc[ni][3] - mn1); sum1 += sacc[ni][3];
        }
        sum0 += __shfl_xor_sync(0xffffffffu, sum0, 1);
        sum0 += __shfl_xor_sync(0xffffffffu, sum0, 2);
        sum1 += __shfl_xor_sync(0xffffffffu, sum1, 1);
        sum1 += __shfl_xor_sync(0xffffffffu, sum1, 2);
        l0 = l0 * al0 + sum0; m0 = mn0;
        l1 = l1 * al1 + sum1; m1 = mn1;

#pragma unroll
        for (int ni = 0; ni < 8; ni++) {
            oacc[ni][0] *= al0; oacc[ni][1] *= al0;
            oacc[ni][2] *= al1; oacc[ni][3] *= al1;
        }

        // ---- O += P V : P fragments come straight from sacc
#pragma unroll
        for (int j = 0; j < 4; j++) {
            unsigned paf[4];
            paf[0] = pkh(sacc[2 * j][0],     sacc[2 * j][1]);
            paf[1] = pkh(sacc[2 * j][2],     sacc[2 * j][3]);
            paf[2] = pkh(sacc[2 * j + 1][0], sacc[2 * j + 1][1]);
            paf[3] = pkh(sacc[2 * j + 1][2], sacc[2 * j + 1][3]);
#pragma unroll
            for (int np = 0; np < 4; np++) {
                unsigned vb[4];
                const int row = j * 16 + (lane & 7) + (((lane >> 3) & 1) << 3);
                const int col = np * 16 + ((lane >> 4) << 3);
                ldsm4t(vb, sptr(&vs[row][col]));
                mma16(oacc[np * 2],     paf, &vb[0]);
                mma16(oacc[np * 2 + 1], paf, &vb[2]);
            }
        }
        __syncthreads();
    }

    // epilogue -> g_vals (half, B,S,D layout)
    const float inv0 = 1.0f / l0;
    const float inv1 = 1.0f / l1;
    __half* orow0 = g_vals + ((size_t)b * SS + qbase + qrow0) * DM + h * HD;
    __half* orow1 = g_vals + ((size_t)b * SS + qbase + qrow1) * DM + h * HD;
#pragma unroll
    for (int ni = 0; ni < 8; ni++) {
        const int col = ni * 8 + 2 * q;
        *(unsigned*)&orow0[col] = pkh(oacc[ni][0] * inv0, oacc[ni][1] * inv0);
        *(unsigned*)&orow1[col] = pkh(oacc[ni][2] * inv1, oacc[ni][3] * inv1);
    }
}

// ---------------------------------------------------------------------------
extern "C" void kernel_launch(void* const* d_in, const int* in_sizes, int n_in,
                              void* d_out, int out_size)
{
    const float* x    = (const float*)d_in[0];
    const float* y    = (const float*)d_in[1];
    const float* mask = (const float*)d_in[2];
    const float* Wkv  = (const float*)d_in[3];
    const float* bkv  = (const float*)d_in[4];
    const float* Wq   = (const float*)d_in[5];
    const float* bq   = (const float*)d_in[6];
    const float* Wo   = (const float*)d_in[7];
    const float* bo   = (const float*)d_in[8];
    float* out = (float*)d_out;

    void* vals_ptr = nullptr;
    cudaGetSymbolAddress(&vals_ptr, g_vals);

    const dim3 blk(256);
    const int M = BB * SS;  // 4096

    gemm_h<0, false><<<dim3(DM / 128, M / 128), blk>>>(y, Wq, bq, nullptr, DM, DM);
    gemm_h<1, false><<<dim3(2 * DM / 128, M / 128), blk>>>(x, Wkv, bkv, nullptr, 2 * DM, DM);

    attn_h<<<dim3(SS / 128, BB * NH), blk>>>(mask);

    gemm_h<2, true><<<dim3(DM / 128, M / 128), blk>>>(vals_ptr, Wo, bo, out, DM, DM);
}

// round 5
// speedup vs baseline: 4.1244x; 1.2752x over previous
#include <cuda_runtime.h>
#include <cuda_fp16.h>
#include <cstdint>
#include <math.h>

#define BB 2
#define SS 2048
#define DM 1024
#define NH 16
#define HD 64

// fp16 scratch (device globals: allocation-free per harness rules)
__device__ __half g_q[BB * NH * SS * HD];     // [b][h][s][c], pre-scaled by 1/8
__device__ __half g_k[BB * NH * SS * HD];     // [b][h][s][c]
__device__ __half g_v[BB * NH * SS * HD];     // [b][h][s][c]
__device__ __half g_vals[BB * SS * DM];       // [b][s][h*64+c]

// ---------------------------------------------------------------------------
// helpers
// ---------------------------------------------------------------------------
__device__ __forceinline__ unsigned pkh(float a, float b) {
    __half2 h = __floats2half2_rn(a, b);
    return *reinterpret_cast<unsigned*>(&h);
}
__device__ __forceinline__ unsigned sptr(const void* p) {
    return (unsigned)__cvta_generic_to_shared(p);
}
__device__ __forceinline__ void ldsm4(unsigned* r, unsigned addr) {
    asm volatile("ldmatrix.sync.aligned.m8n8.x4.shared.b16 {%0,%1,%2,%3},[%4];"
                 : "=r"(r[0]), "=r"(r[1]), "=r"(r[2]), "=r"(r[3]) : "r"(addr));
}
__device__ __forceinline__ void ldsm4t(unsigned* r, unsigned addr) {
    asm volatile("ldmatrix.sync.aligned.m8n8.x4.trans.shared.b16 {%0,%1,%2,%3},[%4];"
                 : "=r"(r[0]), "=r"(r[1]), "=r"(r[2]), "=r"(r[3]) : "r"(addr));
}
__device__ __forceinline__ void mma16(float* d, const unsigned* a, const unsigned* b) {
    asm volatile(
        "mma.sync.aligned.m16n8k16.row.col.f32.f16.f16.f32 "
        "{%0,%1,%2,%3},{%4,%5,%6,%7},{%8,%9},{%0,%1,%2,%3};"
        : "+f"(d[0]), "+f"(d[1]), "+f"(d[2]), "+f"(d[3])
        : "r"(a[0]), "r"(a[1]), "r"(a[2]), "r"(a[3]), "r"(b[0]), "r"(b[1]));
}

// ---------------------------------------------------------------------------
// epilogue scatter
// ---------------------------------------------------------------------------
template <int MODE>
__device__ __forceinline__ void store2(int r, int c0, float v0, float v1,
                                       float* __restrict__ Cout, int N)
{
    const int b = r >> 11;
    const int s = r & 2047;
    if (MODE == 0) {
        const int h = c0 >> 6, cc = c0 & 63;
        const size_t idx = (((size_t)(b * NH + h) * SS) + s) * HD + cc;
        *(unsigned*)&g_q[idx] = pkh(v0 * 0.125f, v1 * 0.125f);
    } else if (MODE == 1) {
        const int h = c0 >> 7, t = c0 & 127;
        if (t < HD) {
            const size_t idx = (((size_t)(b * NH + h) * SS) + s) * HD + t;
            *(unsigned*)&g_k[idx] = pkh(v0, v1);
        } else {
            const size_t idx = (((size_t)(b * NH + h) * SS) + s) * HD + (t - HD);
            *(unsigned*)&g_v[idx] = pkh(v0, v1);
        }
    } else {
        *(float2*)&Cout[(size_t)r * N + c0] = make_float2(v0, v1);
    }
}

// ---------------------------------------------------------------------------
// Double-buffered fp16 GEMM core. 128x128 tile, K-chunk 32, 8 warps (2m x 4n),
// warp tile 64x32, mma.m16n8k16 + ldmatrix. ONE __syncthreads per chunk.
// As: [2*128][40], Bs: [2*32][136]
// ---------------------------------------------------------------------------
template <int MODE, bool AHALF>
__device__ __forceinline__ void gemm_core(
    const void* __restrict__ Av, const float* __restrict__ W,
    const float* __restrict__ bias, float* __restrict__ Cout,
    int N, int K, int brow, int bcol,
    __half (*As)[40], __half (*Bs)[136])
{
    const int tid  = threadIdx.x;
    const int lane = tid & 31;
    const int w    = tid >> 5;
    const int wm   = (w >> 2) * 64;
    const int wn   = (w & 3) * 32;

    const int ar = tid >> 1;            // 0..127
    const int ac = (tid & 1) * 16;      // 0,16
    const int br = tid >> 3;            // 0..31
    const int bc = (tid & 7) * 16;      // 0..112

    const float*  Af = (const float*)Av;
    const __half* Ah = (const __half*)Av;

    float acc[4][4][4];
#pragma unroll
    for (int mi = 0; mi < 4; mi++)
#pragma unroll
        for (int ni = 0; ni < 4; ni++)
#pragma unroll
            for (int e = 0; e < 4; e++) acc[mi][ni][e] = 0.f;

    float4 pa[4];
    uint4  pah[2];
    float4 pb[4];

    // ---- prefetch chunk 0 into regs
    if (AHALF) {
        pah[0] = *(const uint4*)(Ah + (size_t)(brow + ar) * K + ac);
        pah[1] = *(const uint4*)(Ah + (size_t)(brow + ar) * K + ac + 8);
    } else {
#pragma unroll
        for (int i = 0; i < 4; i++)
            pa[i] = *(const float4*)(Af + (size_t)(brow + ar) * K + ac + i * 4);
    }
#pragma unroll
    for (int i = 0; i < 4; i++)
        pb[i] = *(const float4*)(W + (size_t)br * N + bcol + bc + i * 4);

    // ---- store chunk 0 into buffer 0
    {
        if (AHALF) {
            *(uint4*)&As[ar][ac]     = pah[0];
            *(uint4*)&As[ar][ac + 8] = pah[1];
        } else {
            uint4 u0, u1;
            u0.x = pkh(pa[0].x, pa[0].y); u0.y = pkh(pa[0].z, pa[0].w);
            u0.z = pkh(pa[1].x, pa[1].y); u0.w = pkh(pa[1].z, pa[1].w);
            u1.x = pkh(pa[2].x, pa[2].y); u1.y = pkh(pa[2].z, pa[2].w);
            u1.z = pkh(pa[3].x, pa[3].y); u1.w = pkh(pa[3].z, pa[3].w);
            *(uint4*)&As[ar][ac]     = u0;
            *(uint4*)&As[ar][ac + 8] = u1;
        }
        uint4 v0, v1;
        v0.x = pkh(pb[0].x, pb[0].y); v0.y = pkh(pb[0].z, pb[0].w);
        v0.z = pkh(pb[1].x, pb[1].y); v0.w = pkh(pb[1].z, pb[1].w);
        v1.x = pkh(pb[2].x, pb[2].y); v1.y = pkh(pb[2].z, pb[2].w);
        v1.z = pkh(pb[3].x, pb[3].y); v1.w = pkh(pb[3].z, pb[3].w);
        *(uint4*)&Bs[br][bc]     = v0;
        *(uint4*)&Bs[br][bc + 8] = v1;
    }

    const int NC = K / 32;
    for (int c = 0; c < NC; c++) {
        __syncthreads();

        // prefetch chunk c+1 (overlaps with compute below)
        if (c + 1 < NC) {
            const int kn = (c + 1) * 32;
            if (AHALF) {
                pah[0] = *(const uint4*)(Ah + (size_t)(brow + ar) * K + kn + ac);
                pah[1] = *(const uint4*)(Ah + (size_t)(brow + ar) * K + kn + ac + 8);
            } else {
#pragma unroll
                for (int i = 0; i < 4; i++)
                    pa[i] = *(const float4*)(Af + (size_t)(brow + ar) * K + kn + ac + i * 4);
            }
#pragma unroll
            for (int i = 0; i < 4; i++)
                pb[i] = *(const float4*)(W + (size_t)(kn + br) * N + bcol + bc + i * 4);
        }

        // compute on buffer (c & 1)
        const int aoff = (c & 1) * 128;
        const int boff = (c & 1) * 32;
#pragma unroll
        for (int ks2 = 0; ks2 < 2; ks2++) {
            const int kk = ks2 * 16;
            unsigned af[4][4];
#pragma unroll
            for (int mi = 0; mi < 4; mi++)
                ldsm4(af[mi], sptr(&As[aoff + wm + mi * 16 + (lane & 15)][kk + ((lane >> 4) << 3)]));
            unsigned bfr[2][4];
#pragma unroll
            for (int np = 0; np < 2; np++) {
                const int row = boff + kk + (lane & 7) + (((lane >> 3) & 1) << 3);
                const int col = wn + np * 16 + ((lane >> 4) << 3);
                ldsm4t(bfr[np], sptr(&Bs[row][col]));
            }
#pragma unroll
            for (int mi = 0; mi < 4; mi++)
#pragma unroll
                for (int ni = 0; ni < 4; ni++)
                    mma16(acc[mi][ni], af[mi], &bfr[ni >> 1][(ni & 1) * 2]);
        }

        // store chunk c+1 into the other buffer
        if (c + 1 < NC) {
            const int ao = ((c + 1) & 1) * 128;
            const int bo = ((c + 1) & 1) * 32;
            if (AHALF) {
                *(uint4*)&As[ao + ar][ac]     = pah[0];
                *(uint4*)&As[ao + ar][ac + 8] = pah[1];
            } else {
                uint4 u0, u1;
                u0.x = pkh(pa[0].x, pa[0].y); u0.y = pkh(pa[0].z, pa[0].w);
                u0.z = pkh(pa[1].x, pa[1].y); u0.w = pkh(pa[1].z, pa[1].w);
                u1.x = pkh(pa[2].x, pa[2].y); u1.y = pkh(pa[2].z, pa[2].w);
                u1.z = pkh(pa[3].x, pa[3].y); u1.w = pkh(pa[3].z, pa[3].w);
                *(uint4*)&As[ao + ar][ac]     = u0;
                *(uint4*)&As[ao + ar][ac + 8] = u1;
            }
            uint4 v0, v1;
            v0.x = pkh(pb[0].x, pb[0].y); v0.y = pkh(pb[0].z, pb[0].w);
            v0.z = pkh(pb[1].x, pb[1].y); v0.w = pkh(pb[1].z, pb[1].w);
            v1.x = pkh(pb[2].x, pb[2].y); v1.y = pkh(pb[2].z, pb[2].w);
            v1.z = pkh(pb[3].x, pb[3].y); v1.w = pkh(pb[3].z, pb[3].w);
            *(uint4*)&Bs[bo + br][bc]     = v0;
            *(uint4*)&Bs[bo + br][bc + 8] = v1;
        }
    }

    // epilogue
    const int g = lane >> 2, q = lane & 3;
#pragma unroll
    for (int mi = 0; mi < 4; mi++) {
        const int r0 = brow + wm + mi * 16 + g;
        const int r1 = r0 + 8;
#pragma unroll
        for (int ni = 0; ni < 4; ni++) {
            const int c0 = bcol + wn + ni * 8 + 2 * q;
            const float bia0 = bias[c0], bia1 = bias[c0 + 1];
            store2<MODE>(r0, c0, acc[mi][ni][0] + bia0, acc[mi][ni][1] + bia1, Cout, N);
            store2<MODE>(r1, c0, acc[mi][ni][2] + bia0, acc[mi][ni][3] + bia1, Cout, N);
        }
    }
}

// ---------------------------------------------------------------------------
// Fused q + kv projection: grid.x = 8 (q tiles) + 16 (kv tiles) = 24
// ---------------------------------------------------------------------------
__global__ __launch_bounds__(256)
void proj_fused(const float* __restrict__ y, const float* __restrict__ Wq,
                const float* __restrict__ bq,
                const float* __restrict__ x, const float* __restrict__ Wkv,
                const float* __restrict__ bkv)
{
    __shared__ __half As[2 * 128][40];
    __shared__ __half Bs[2 * 32][136];

    const int brow = blockIdx.y * 128;
    if (blockIdx.x < 8) {
        const int bcol = blockIdx.x * 128;
        gemm_core<0, false>(y, Wq, bq, nullptr, DM, DM, brow, bcol, As, Bs);
    } else {
        const int bcol = (blockIdx.x - 8) * 128;
        gemm_core<1, false>(x, Wkv, bkv, nullptr, 2 * DM, DM, brow, bcol, As, Bs);
    }
}

// ---------------------------------------------------------------------------
// Output projection: A = g_vals (fp16), fp32 out
// ---------------------------------------------------------------------------
__global__ __launch_bounds__(256)
void gemm_o(const void* __restrict__ Av, const float* __restrict__ W,
            const float* __restrict__ bias, float* __restrict__ Cout)
{
    __shared__ __half As[2 * 128][40];
    __shared__ __half Bs[2 * 32][136];
    gemm_core<2, true>(Av, W, bias, Cout, DM, DM,
                       blockIdx.y * 128, blockIdx.x * 128, As, Bs);
}

// ---------------------------------------------------------------------------
// Flash attention fp16, double-buffered K/V tiles, one sync per tile.
// 128 q-rows/CTA, 8 warps, key tile 64.
// ---------------------------------------------------------------------------
__global__ __launch_bounds__(256)
void attn_h(const float* __restrict__ mask)
{
    extern __shared__ __half smh[];
    __half (*qs)[72] = (__half(*)[72])smh;                   // 128 x 72
    __half (*ks)[72] = (__half(*)[72])(smh + 128 * 72);      // 2 x 64 x 72
    __half (*vs)[72] = (__half(*)[72])(smh + 128 * 72 + 2 * 64 * 72);

    const int tid  = threadIdx.x;
    const int lane = tid & 31;
    const int w    = tid >> 5;
    const int g    = lane >> 2;
    const int q    = lane & 3;

    const int bh    = blockIdx.y;
    const int b     = bh >> 4;
    const int h     = bh & 15;
    const int qbase = blockIdx.x * 128;

    const __half* qg  = g_q + ((size_t)bh * SS + qbase) * HD;
    const __half* kgb = g_k + (size_t)bh * SS * HD;
    const __half* vgb = g_v + (size_t)bh * SS * HD;

    // load q tile (pure copy; already fp16 + pre-scaled)
    {
        const int r = tid >> 1, cs = (tid & 1) * 32;
#pragma unroll
        for (int i = 0; i < 4; i++)
            *(uint4*)&qs[r][cs + i * 8] = *(const uint4*)(qg + (size_t)r * HD + cs + i * 8);
    }

    const int tr = tid >> 2;            // 0..63
    const int tc = (tid & 3) * 16;      // 0,16,32,48

    // prefetch tile 0 and store into buffer 0
    uint4 kreg[2], vreg[2];
#pragma unroll
    for (int i = 0; i < 2; i++) {
        kreg[i] = *(const uint4*)(kgb + (size_t)tr * HD + tc + i * 8);
        vreg[i] = *(const uint4*)(vgb + (size_t)tr * HD + tc + i * 8);
    }
    *(uint4*)&ks[tr][tc]     = kreg[0];
    *(uint4*)&ks[tr][tc + 8] = kreg[1];
    *(uint4*)&vs[tr][tc]     = vreg[0];
    *(uint4*)&vs[tr][tc + 8] = vreg[1];

    __syncthreads();

    // hoist q a-fragments (invariant across key tiles)
    unsigned qa[4][4];
#pragma unroll
    for (int kk4 = 0; kk4 < 4; kk4++)
        ldsm4(qa[kk4], sptr(&qs[w * 16 + (lane & 15)][kk4 * 16 + ((lane >> 4) << 3)]));

    float oacc[8][4];
#pragma unroll
    for (int ni = 0; ni < 8; ni++)
#pragma unroll
        for (int e = 0; e < 4; e++) oacc[ni][e] = 0.f;
    float m0 = -1e30f, m1 = -1e30f, l0 = 0.f, l1 = 0.f;

    const int qrow0 = w * 16 + g;
    const int qrow1 = qrow0 + 8;
    const float* mrow0 = mask + ((size_t)b * SS + qbase + qrow0) * SS;
    const float* mrow1 = mask + ((size_t)b * SS + qbase + qrow1) * SS;

    const int NT = SS / 64;
    for (int kt = 0; kt < NT; kt++) {
        const int kbase = kt * 64;
        const int cb = (kt & 1) * 64;       // compute buffer row offset
        const int nb = ((kt + 1) & 1) * 64; // next buffer row offset

        // prefetch next tile (overlaps compute)
        if (kt + 1 < NT) {
            const size_t off = (size_t)(kbase + 64 + tr) * HD + tc;
#pragma unroll
            for (int i = 0; i < 2; i++) {
                kreg[i] = *(const uint4*)(kgb + off + i * 8);
                vreg[i] = *(const uint4*)(vgb + off + i * 8);
            }
        }

        // ---- S = Q K^T (16 x 64 per warp)
        float sacc[8][4];
#pragma unroll
        for (int ni = 0; ni < 8; ni++)
#pragma unroll
            for (int e = 0; e < 4; e++) sacc[ni][e] = 0.f;

#pragma unroll
        for (int kk4 = 0; kk4 < 4; kk4++) {
#pragma unroll
            for (int np = 0; np < 4; np++) {
                unsigned kb[4];
                const int row = cb + np * 16 + (lane & 7) + (((lane >> 4) & 1) << 3);
                const int col = kk4 * 16 + (((lane >> 3) & 1) << 3);
                ldsm4(kb, sptr(&ks[row][col]));
                mma16(sacc[np * 2],     qa[kk4], &kb[0]);
                mma16(sacc[np * 2 + 1], qa[kk4], &kb[2]);
            }
        }

        // ---- + mask
#pragma unroll
        for (int ni = 0; ni < 8; ni++) {
            const int col = kbase + ni * 8 + 2 * q;
            const float2 mv0 = *(const float2*)(mrow0 + col);
            const float2 mv1 = *(const float2*)(mrow1 + col);
            sacc[ni][0] += mv0.x; sacc[ni][1] += mv0.y;
            sacc[ni][2] += mv1.x; sacc[ni][3] += mv1.y;
        }

        // ---- online softmax
        float mx0 = -1e30f, mx1 = -1e30f;
#pragma unroll
        for (int ni = 0; ni < 8; ni++) {
            mx0 = fmaxf(mx0, fmaxf(sacc[ni][0], sacc[ni][1]));
            mx1 = fmaxf(mx1, fmaxf(sacc[ni][2], sacc[ni][3]));
        }
        mx0 = fmaxf(mx0, __shfl_xor_sync(0xffffffffu, mx0, 1));
        mx0 = fmaxf(mx0, __shfl_xor_sync(0xffffffffu, mx0, 2));
        mx1 = fmaxf(mx1, __shfl_xor_sync(0xffffffffu, mx1, 1));
        mx1 = fmaxf(mx1, __shfl_xor_sync(0xffffffffu, mx1, 2));

        const float mn0 = fmaxf(m0, mx0);
        const float mn1 = fmaxf(m1, mx1);
        const float al0 = __expf(m0 - mn0);
        const float al1 = __expf(m1 - mn1);
        float sum0 = 0.f, sum1 = 0.f;
#pragma unroll
        for (int ni = 0; ni < 8; ni++) {
            sacc[ni][0] = __expf(sacc[ni][0] - mn0); sum0 += sacc[ni][0];
            sacc[ni][1] = __expf(sacc[ni][1] - mn0); sum0 += sacc[ni][1];
            sacc[ni][2] = __expf(sacc[ni][2] - mn1); sum1 += sacc[ni][2];
            sacc[ni][3] = __expf(sacc[ni][3] - mn1); sum1 += sacc[ni][3];
        }
        sum0 += __shfl_xor_sync(0xffffffffu, sum0, 1);
        sum0 += __shfl_xor_sync(0xffffffffu, sum0, 2);
        sum1 += __shfl_xor_sync(0xffffffffu, sum1, 1);
        sum1 += __shfl_xor_sync(0xffffffffu, sum1, 2);
        l0 = l0 * al0 + sum0; m0 = mn0;
        l1 = l1 * al1 + sum1; m1 = mn1;

#pragma unroll
        for (int ni = 0; ni < 8; ni++) {
            oacc[ni][0] *= al0; oacc[ni][1] *= al0;
            oacc[ni][2] *= al1; oacc[ni][3] *= al1;
        }

        // ---- O += P V : P fragments come straight from sacc
#pragma unroll
        for (int j = 0; j < 4; j++) {
            unsigned paf[4];
            paf[0] = pkh(sacc[2 * j][0],     sacc[2 * j][1]);
            paf[1] = pkh(sacc[2 * j][2],     sacc[2 * j][3]);
            paf[2] = pkh(sacc[2 * j + 1][0], sacc[2 * j + 1][1]);
            paf[3] = pkh(sacc[2 * j + 1][2], sacc[2 * j + 1][3]);
#pragma unroll
            for (int np = 0; np < 4; np++) {
                unsigned vb[4];
                const int row = cb + j * 16 + (lane & 7) + (((lane >> 3) & 1) << 3);
                const int col = np * 16 + ((lane >> 4) << 3);
                ldsm4t(vb, sptr(&vs[row][col]));
                mma16(oacc[np * 2],     paf, &vb[0]);
                mma16(oacc[np * 2 + 1], paf, &vb[2]);
            }
        }

        // store next tile into other buffer, single sync
        if (kt + 1 < NT) {
            *(uint4*)&ks[nb + tr][tc]     = kreg[0];
            *(uint4*)&ks[nb + tr][tc + 8] = kreg[1];
            *(uint4*)&vs[nb + tr][tc]     = vreg[0];
            *(uint4*)&vs[nb + tr][tc + 8] = vreg[1];
            __syncthreads();
        }
    }

    // epilogue -> g_vals (half, B,S,D layout)
    const float inv0 = 1.0f / l0;
    const float inv1 = 1.0f / l1;
    __half* orow0 = g_vals + ((size_t)b * SS + qbase + qrow0) * DM + h * HD;
    __half* orow1 = g_vals + ((size_t)b * SS + qbase + qrow1) * DM + h * HD;
#pragma unroll
    for (int ni = 0; ni < 8; ni++) {
        const int col = ni * 8 + 2 * q;
        *(unsigned*)&orow0[col] = pkh(oacc[ni][0] * inv0, oacc[ni][1] * inv0);
        *(unsigned*)&orow1[col] = pkh(oacc[ni][2] * inv1, oacc[ni][3] * inv1);
    }
}

// ---------------------------------------------------------------------------
extern "C" void kernel_launch(void* const* d_in, const int* in_sizes, int n_in,
                              void* d_out, int out_size)
{
    const float* x    = (const float*)d_in[0];
    const float* y    = (const float*)d_in[1];
    const float* mask = (const float*)d_in[2];
    const float* Wkv  = (const float*)d_in[3];
    const float* bkv  = (const float*)d_in[4];
    const float* Wq   = (const float*)d_in[5];
    const float* bq   = (const float*)d_in[6];
    const float* Wo   = (const float*)d_in[7];
    const float* bo   = (const float*)d_in[8];
    float* out = (float*)d_out;

    void* vals_ptr = nullptr;
    cudaGetSymbolAddress(&vals_ptr, g_vals);

    const dim3 blk(256);
    const int M = BB * SS;  // 4096

    // fused q + kv projection
    proj_fused<<<dim3(24, M / 128), blk>>>(y, Wq, bq, x, Wkv, bkv);

    // attention (dynamic smem: 128*72 + 2*64*72 + 2*64*72 halves = 55296 B)
    const int smem_attn = (128 * 72 + 4 * 64 * 72) * (int)sizeof(__half);
    cudaFuncSetAttribute(attn_h, cudaFuncAttributeMaxDynamicSharedMemorySize, smem_attn);
    attn_h<<<dim3(SS / 128, BB * NH), blk, smem_attn>>>(mask);

    // output projection
    gemm_o<<<dim3(DM / 128, M / 128), blk>>>(vals_ptr, Wo, bo, out);
}